// round 9
// baseline (speedup 1.0000x reference)
#include <cuda_runtime.h>
#include <cuda_bf16.h>

// Zero-initialized at module load; last block resets them at the end of every
// launch, so every run (correctness + each graph replay) starts from zero.
__device__ float    g_sum;
__device__ unsigned g_arrived;
__device__ unsigned g_done;

#define NBLOCKS  148
#define NTHREADS 1024
#define UNROLL   4

// Speculated outcome: S > 0  =>  factor = 4^32 = 2^64 (exact exponent shift).
#define F_GUESS  0x1p64f

__global__ void __launch_bounds__(NTHREADS, 1)
fused_kernel(const float4* __restrict__ in, float4* __restrict__ out, long long n4) {
    // ---- balanced contiguous split in 16KB subtiles (NTHREADS float4 each).
    // 8192 subtiles / 148 blocks = 55 or 56 -> max skew 1.8% (was 7%). ----
    long long nsub = n4 / NTHREADS;              // full subtiles
    long long q    = nsub / gridDim.x;
    long long r    = nsub % gridDim.x;
    long long b    = blockIdx.x;
    long long s0   = b * q + (b < r ? b : r);
    long long cnt  = q + (b < r ? 1 : 0);
    long long lo   = s0 * NTHREADS;
    long long hi   = (s0 + cnt) * NTHREADS;
    long long rem0 = nsub * NTHREADS;            // element tail (empty here)

    // ---- phase 1: sum AND speculatively write out = in * F_GUESS.
    // Groups of 4 subtiles -> 4 batched LDG.128 in flight (MLP=4). ----
    float s = 0.0f;
    long long i = lo + threadIdx.x;
    for (; i + 3 * NTHREADS < hi; i += (long long)UNROLL * NTHREADS) {
        float4 v[UNROLL];
        #pragma unroll
        for (int u = 0; u < UNROLL; ++u)
            v[u] = in[i + (long long)u * NTHREADS];
        #pragma unroll
        for (int u = 0; u < UNROLL; ++u) {
            s += (v[u].x + v[u].y) + (v[u].z + v[u].w);
            float4 w;
            w.x = v[u].x * F_GUESS; w.y = v[u].y * F_GUESS;
            w.z = v[u].z * F_GUESS; w.w = v[u].w * F_GUESS;
            out[i + (long long)u * NTHREADS] = w;
        }
    }
    for (; i < hi; i += NTHREADS) {              // <=3 leftover subtiles
        float4 v = in[i];
        s += (v.x + v.y) + (v.z + v.w);
        float4 w;
        w.x = v.x * F_GUESS; w.y = v.y * F_GUESS;
        w.z = v.z * F_GUESS; w.w = v.w * F_GUESS;
        out[i] = w;
    }
    // element remainder (empty for this shape; kept for generality)
    for (long long j = rem0 + (long long)blockIdx.x * NTHREADS + threadIdx.x;
         j < n4; j += (long long)gridDim.x * NTHREADS) {
        float4 v = in[j];
        s += (v.x + v.y) + (v.z + v.w);
        float4 w;
        w.x = v.x * F_GUESS; w.y = v.y * F_GUESS;
        w.z = v.z * F_GUESS; w.w = v.w * F_GUESS;
        out[j] = w;
    }

    #pragma unroll
    for (int o = 16; o > 0; o >>= 1)
        s += __shfl_xor_sync(0xffffffffu, s, o);

    __shared__ float sm[32];
    __shared__ float s_factor;
    int lane = threadIdx.x & 31;
    int warp = threadIdx.x >> 5;
    if (lane == 0) sm[warp] = s;
    __syncthreads();
    if (warp == 0) {
        s = (lane < (NTHREADS >> 5)) ? sm[lane] : 0.0f;
        #pragma unroll
        for (int o = 16; o > 0; o >>= 1)
            s += __shfl_xor_sync(0xffffffffu, s, o);
        if (lane == 0) {
            atomicAdd(&g_sum, s);
            __threadfence();
            atomicAdd(&g_arrived, 1u);
        }
    }

    // ---- grid barrier: wait for all blocks' partials ----
    if (threadIdx.x == 0) {
        volatile unsigned* pa = &g_arrived;
        while (*pa < gridDim.x) { /* all 148 blocks resident: spin is safe */ }
        __threadfence();
        volatile float* ps = &g_sum;
        float S = *ps;
        // S>0: 4^32 = 2^64.  S<0: -2*4^31 = -2^63.  S==0: (-2)^32 = 2^32.
        s_factor = (S > 0.0f) ? 0x1p64f : ((S < 0.0f) ? -0x1p63f : 0x1p32f);
    }
    __syncthreads();
    float f = s_factor;

    // ---- phase 2 (mispredict repair only): rewrite with the correct factor. ----
    if (f != F_GUESS) {
        for (long long k = lo + threadIdx.x; k < hi; k += NTHREADS) {
            float4 v = in[k];
            v.x *= f; v.y *= f; v.z *= f; v.w *= f;
            out[k] = v;
        }
        for (long long j = rem0 + (long long)blockIdx.x * NTHREADS + threadIdx.x;
             j < n4; j += (long long)gridDim.x * NTHREADS) {
            float4 v = in[j];
            v.x *= f; v.y *= f; v.z *= f; v.w *= f;
            out[j] = v;
        }
    }

    // ---- epilogue: last block resets globals for the next replay ----
    __syncthreads();
    if (threadIdx.x == 0) {
        __threadfence();
        unsigned d = atomicAdd(&g_done, 1u);
        if (d == gridDim.x - 1) {
            g_sum     = 0.0f;
            g_arrived = 0u;
            g_done    = 0u;
            __threadfence();
        }
    }
}

extern "C" void kernel_launch(void* const* d_in, const int* in_sizes, int n_in,
                              void* d_out, int out_size) {
    const float4* in  = (const float4*)d_in[0];
    float4*       out = (float4*)d_out;
    long long n  = (long long)in_sizes[0];   // 32*1024*1024
    long long n4 = n >> 2;                   // float4 count (n divisible by 4)

    fused_kernel<<<NBLOCKS, NTHREADS>>>(in, out, n4);
}

// round 10
// speedup vs baseline: 1.1276x; 1.1276x over previous
#include <cuda_runtime.h>
#include <cuda_bf16.h>

// Zero-initialized at module load; last block resets them at the end of every
// launch, so every run (correctness + each graph replay) starts from zero.
__device__ float    g_sum;
__device__ unsigned g_arrived;
__device__ unsigned g_done;
__device__ unsigned g_tile;     // dynamic work-stealing tile counter

#define NBLOCKS  148
#define NTHREADS 1024
#define UNROLL   4
#define TILE     (NTHREADS * UNROLL)   // 4096 float4 = 64 KB per tile

// Speculated outcome: S > 0  =>  factor = 4^32 = 2^64 (exact exponent shift).
#define F_GUESS  0x1p64f

__global__ void __launch_bounds__(NTHREADS, 1)
fused_kernel(const float4* __restrict__ in, float4* __restrict__ out, long long n4) {
    long long ftiles = n4 / TILE;          // 2048 full tiles for this shape
    long long rem0   = ftiles * TILE;      // element tail start (== n4 here)

    __shared__ float    sm[32];
    __shared__ float    s_factor;
    __shared__ unsigned s_tile[2];         // double-buffered next-tile index

    // ---- phase 1: dynamic tiles. Fetch tile k+1 while tile k's loads are in
    // flight, so the ATOMG latency is hidden under the memory-bound body. ----
    float s = 0.0f;
    if (threadIdx.x == 0) s_tile[0] = atomicAdd(&g_tile, 1u);
    __syncthreads();
    unsigned t   = s_tile[0];
    int      buf = 0;
    while ((long long)t < ftiles) {
        if (threadIdx.x == 0) s_tile[buf ^ 1] = atomicAdd(&g_tile, 1u);

        long long base = (long long)t * TILE + threadIdx.x;
        float4 v[UNROLL];
        #pragma unroll
        for (int u = 0; u < UNROLL; ++u)
            v[u] = in[base + (long long)u * NTHREADS];
        #pragma unroll
        for (int u = 0; u < UNROLL; ++u) {
            s += (v[u].x + v[u].y) + (v[u].z + v[u].w);
            float4 w;
            w.x = v[u].x * F_GUESS; w.y = v[u].y * F_GUESS;
            w.z = v[u].z * F_GUESS; w.w = v[u].w * F_GUESS;
            out[base + (long long)u * NTHREADS] = w;
        }

        __syncthreads();
        buf ^= 1;
        t = s_tile[buf];
    }
    // element remainder (empty for this shape; kept for generality)
    for (long long j = rem0 + (long long)blockIdx.x * NTHREADS + threadIdx.x;
         j < n4; j += (long long)gridDim.x * NTHREADS) {
        float4 v = in[j];
        s += (v.x + v.y) + (v.z + v.w);
        float4 w;
        w.x = v.x * F_GUESS; w.y = v.y * F_GUESS;
        w.z = v.z * F_GUESS; w.w = v.w * F_GUESS;
        out[j] = w;
    }

    #pragma unroll
    for (int o = 16; o > 0; o >>= 1)
        s += __shfl_xor_sync(0xffffffffu, s, o);

    int lane = threadIdx.x & 31;
    int warp = threadIdx.x >> 5;
    if (lane == 0) sm[warp] = s;
    __syncthreads();
    if (warp == 0) {
        s = (lane < (NTHREADS >> 5)) ? sm[lane] : 0.0f;
        #pragma unroll
        for (int o = 16; o > 0; o >>= 1)
            s += __shfl_xor_sync(0xffffffffu, s, o);
        if (lane == 0) {
            atomicAdd(&g_sum, s);
            __threadfence();
            atomicAdd(&g_arrived, 1u);
        }
    }

    // ---- grid barrier: wait for all blocks' partials ----
    if (threadIdx.x == 0) {
        volatile unsigned* pa = &g_arrived;
        while (*pa < gridDim.x) { /* all 148 blocks resident: spin is safe */ }
        __threadfence();
        volatile float* ps = &g_sum;
        float S = *ps;
        // S>0: 4^32 = 2^64.  S<0: -2*4^31 = -2^63.  S==0: (-2)^32 = 2^32.
        s_factor = (S > 0.0f) ? 0x1p64f : ((S < 0.0f) ? -0x1p63f : 0x1p32f);
    }
    __syncthreads();
    float f = s_factor;

    // ---- phase 2 (mispredict repair only): rewrite with correct factor. ----
    if (f != F_GUESS) {
        for (long long k = (long long)blockIdx.x * NTHREADS + threadIdx.x;
             k < n4; k += (long long)gridDim.x * NTHREADS) {
            float4 v = in[k];
            v.x *= f; v.y *= f; v.z *= f; v.w *= f;
            out[k] = v;
        }
    }

    // ---- epilogue: last block resets globals for the next replay ----
    __syncthreads();
    if (threadIdx.x == 0) {
        __threadfence();
        unsigned d = atomicAdd(&g_done, 1u);
        if (d == gridDim.x - 1) {
            g_sum     = 0.0f;
            g_arrived = 0u;
            g_done    = 0u;
            g_tile    = 0u;
            __threadfence();
        }
    }
}

extern "C" void kernel_launch(void* const* d_in, const int* in_sizes, int n_in,
                              void* d_out, int out_size) {
    const float4* in  = (const float4*)d_in[0];
    float4*       out = (float4*)d_out;
    long long n  = (long long)in_sizes[0];   // 32*1024*1024
    long long n4 = n >> 2;                   // float4 count (n divisible by 4)

    fused_kernel<<<NBLOCKS, NTHREADS>>>(in, out, n4);
}